// round 13
// baseline (speedup 1.0000x reference)
#include <cuda_runtime.h>

#define NQ 12
#define NT 256

typedef unsigned long long u64;

// ---- packed f32x2 helpers ----
static __device__ __forceinline__ u64 pack2(float lo, float hi) {
    u64 v; asm("mov.b64 %0, {%1, %2};" : "=l"(v) : "f"(lo), "f"(hi)); return v;
}
static __device__ __forceinline__ void unpack2(u64 v, float &lo, float &hi) {
    asm("mov.b64 {%0, %1}, %2;" : "=f"(lo), "=f"(hi) : "l"(v));
}
static __device__ __forceinline__ u64 fma2(u64 a, u64 b, u64 c) {
    u64 d; asm("fma.rn.f32x2 %0, %1, %2, %3;" : "=l"(d) : "l"(a), "l"(b), "l"(c)); return d;
}
static __device__ __forceinline__ u64 mul2(u64 a, u64 b) {
    u64 d; asm("mul.rn.f32x2 %0, %1, %2;" : "=l"(d) : "l"(a), "l"(b)); return d;
}
static __device__ __forceinline__ u64 add2(u64 a, u64 b) {
    u64 d; asm("add.rn.f32x2 %0, %1, %2;" : "=l"(d) : "l"(a), "l"(b)); return d;
}

// One CTA simulates TWO batch elements: lo half of every u64 = element A,
// hi half = element B. Per element: slot s = wp*512 + lane*16 + r, r = 4-bit
// register index (16 amps/thread/element). Qubit j <-> logical bit (11-j).
// Variational gates use RX(th) = cos * (I - i tan X); the cos product C is
// applied as C^2 to the outputs (identical for both elements since w shared).
// Transpose buffer interleaves (X, Y) per slot -> 128-bit LDS/STS for T1/T2.

template<int B>
__device__ __forceinline__ void rx16(u64 (&X)[16], u64 (&Y)[16], u64 t2, u64 tn2) {
    #pragma unroll
    for (int j = 0; j < 16; j++) {
        if (!((j >> B) & 1)) {
            const int j1 = j | (1 << B);
            u64 x0 = X[j], x1 = X[j1], y0 = Y[j], y1 = Y[j1];
            X[j]  = fma2(t2,  y1, x0);
            X[j1] = fma2(t2,  y0, x1);
            Y[j]  = fma2(tn2, x1, y0);
            Y[j1] = fma2(tn2, x0, y1);
        }
    }
}

__device__ __forceinline__ void frame4(u64 (&X)[16], u64 (&Y)[16], const float2* t) {
    #pragma unroll
    for (int q = 0; q < 4; q++) {
        float2 tq = t[q];                       // (tan, -tan)
        u64 t2 = pack2(tq.x, tq.x), tn2 = pack2(tq.y, tq.y);
        if (q == 0) rx16<0>(X, Y, t2, tn2);
        else if (q == 1) rx16<1>(X, Y, t2, tn2);
        else if (q == 2) rx16<2>(X, Y, t2, tn2);
        else rx16<3>(X, Y, t2, tn2);
    }
}

__global__ void __launch_bounds__(NT, 3)
qsim_kernel(const float* __restrict__ x, const float* __restrict__ w,
            float* __restrict__ out) {
    extern __shared__ __align__(16) ulonglong2 sXY[];   // [4096] = 64 KB
    __shared__ float2 trig0[24];   // (cos,sin) input layer, per element
    __shared__ float2 tl[24];      // (tan,-tan) variational, per layer
    __shared__ float  cosv[24];
    __shared__ float  wacc[2 * 8 * 12];

    const int tid  = threadIdx.x;
    const int lane = tid & 31;
    const int wp   = tid >> 5;
    const int blk  = blockIdx.x;

    if (tid < 24) {
        int e = tid / 12, q = tid % 12;
        float th = 0.5f * x[(2 * blk + e) * NQ + (NQ - 1 - q)];
        trig0[e * 12 + q] = make_float2(cosf(th), sinf(th));
    } else if (tid < 48) {
        int t = tid - 24, l = t / 12, q = t % 12;
        float th = 0.5f * w[l * NQ + (NQ - 1 - q)];
        float c = cosf(th), s = sinf(th), tn = s / c;
        tl[l * 12 + q] = make_float2(tn, -tn);
        cosv[t] = c;
    }
    __syncthreads();

    u64 X[16], Y[16];

    // ---- init: product state after input RX layer on |0...0>, per element ----
    {
        float mhA = 1.0f, mhB = 1.0f;
        #pragma unroll
        for (int b = 0; b < 8; b++) {
            float2 tA = trig0[b + 4], tB = trig0[12 + b + 4];
            bool bit = (tid >> b) & 1;
            mhA *= bit ? tA.y : tA.x;
            mhB *= bit ? tB.y : tB.x;
        }
        const int pch = __popc(tid);
        #pragma unroll
        for (int j = 0; j < 16; j++) {
            float mA = mhA, mB = mhB;
            #pragma unroll
            for (int b = 0; b < 4; b++) {
                float2 tA = trig0[b], tB = trig0[12 + b];
                bool bit = (j >> b) & 1;
                mA *= bit ? tA.y : tA.x;
                mB *= bit ? tB.y : tB.x;
            }
            int pc = (pch + __popc(j)) & 3;
            float reA = (pc == 0) ?  mA : (pc == 2) ? -mA : 0.0f;
            float imA = (pc == 1) ? -mA : (pc == 3) ?  mA : 0.0f;
            float reB = (pc == 0) ?  mB : (pc == 2) ? -mB : 0.0f;
            float imB = (pc == 1) ? -mB : (pc == 3) ?  mB : 0.0f;
            X[j] = pack2(reA, reB);
            Y[j] = pack2(imA, imB);
        }
    }

    #pragma unroll 1
    for (int l = 0; l < 2; l++) {
        // frame I: regs = logical 0-3
        frame4(X, Y, &tl[l * 12]);

        // ---- T1: swap slot bits 0-3 <-> 4-7 (warp-local: stripe bits 5-7 = wp) ----
        if (l) __syncthreads();            // layer-1 T3 gathers crossed stripes
        #pragma unroll
        for (int j = 0; j < 16; j++) {
            int a = (j << 8) | (wp << 5) | (lane ^ j);
            sXY[a] = make_ulonglong2(X[j], Y[j]);
        }
        __syncwarp();
        {
            const int g = ((lane & 15) << 8) | (wp << 5) | (lane & 16);
            #pragma unroll
            for (int j = 0; j < 16; j++) {
                ulonglong2 v = sXY[g | (j ^ (lane & 15))];
                X[j] = v.x;
                Y[j] = v.y;
            }
        }

        // frame f1: regs = logical 4-7
        frame4(X, Y, &tl[l * 12 + 4]);

        // ---- T2: swap slot bits 0-3 <-> 8-11 ----
        __syncwarp();                      // T1 gather (own stripe) before overwrite
        #pragma unroll
        for (int j = 0; j < 16; j++) {
            int a = (j << 8) | (wp << 5) | (lane ^ ((j & 1) << 4));
            sXY[a] = make_ulonglong2(X[j], Y[j]);
        }
        __syncthreads();
        {
            const int ru = (lane >> 4) | (wp << 1);
            #pragma unroll
            for (int j = 0; j < 16; j++) {
                int a = (ru << 8) | ((j >> 1) << 5) | (lane & 15)
                      | (((j & 1) ^ (lane >> 4)) << 4);
                ulonglong2 v = sXY[a];
                X[j] = v.x;
                Y[j] = v.y;
            }
        }

        // frame f2: regs = logical 8-11
        frame4(X, Y, &tl[l * 12 + 8]);

        if (l == 0) {
            // ---- T3: back to frame I with all 12 CNOTs folded (64-bit path:
            // the P-permuted gather is provably 2-way conflicted at 16B) ----
            u64* s64 = reinterpret_cast<u64*>(sXY);
            __syncthreads();               // all T2 gathers done before overwrite
            #pragma unroll
            for (int j = 0; j < 16; j++) {
                int a = (j << 8) | (wp << 5) | (lane ^ wp);
                s64[2 * a]     = X[j];
                s64[2 * a + 1] = Y[j];
            }
            __syncthreads();
            #pragma unroll
            for (int j = 0; j < 16; j++) {
                int s = (wp << 9) | (lane << 4) | j;
                int P = ((s ^ (s >> 1)) & 0x3FF)
                      | ((((s >> 10) ^ (s >> 11) ^ s) & 1) << 10)
                      | ((((s >> 11) ^ s) & 1) << 11);
                int a = (P & 0xF00) | (((P >> 5) & 7) << 5)
                      | ((P & 31) ^ ((P >> 5) & 7));
                X[j] = s64[2 * a];
                Y[j] = s64[2 * a + 1];
            }
        }
        // l == 1: stay in frame f2 with pending ring perm; folded below.
    }

    // ---- expectations (frame f2 + pending perm folded into signs) ----
    const u64 one2  = pack2(1.0f, 1.0f);
    const u64 mone2 = pack2(-1.0f, -1.0f);
    u64 Dp, Ep, Fp, Gp;
    {
        u64 P0 = fma2(X[0], X[0], mul2(Y[0], Y[0]));
        Dp = P0; Ep = P0; Fp = P0; Gp = P0;
    }
    #pragma unroll
    for (int j = 1; j < 16; j++) {
        u64 P = fma2(X[j], X[j], mul2(Y[j], Y[j]));
        Dp = fma2((__popc(j)      & 1) ? mone2 : one2, P, Dp);  // r0^r1^r2^r3
        Ep = fma2((__popc(j & 14) & 1) ? mone2 : one2, P, Ep);  // r1^r2^r3
        Fp = fma2((__popc(j & 12) & 1) ? mone2 : one2, P, Fp);  // r2^r3
        Gp = fma2((__popc(j & 7)  & 1) ? mone2 : one2, P, Gp);  // r0^r1^r2
    }

    // Walsh-Hadamard over the 5 lane bits on D and G; allreduce on E, F.
    #pragma unroll
    for (int st = 0; st < 5; st++) {
        const int m = 1 << st;
        u64 sD = __shfl_xor_sync(0xffffffffu, Dp, m);
        u64 sG = __shfl_xor_sync(0xffffffffu, Gp, m);
        u64 sE = __shfl_xor_sync(0xffffffffu, Ep, m);
        u64 sF = __shfl_xor_sync(0xffffffffu, Fp, m);
        u64 sgn = (lane & m) ? mone2 : one2;
        Dp = fma2(sgn, Dp, sD);
        Gp = fma2(sgn, Gp, sG);
        Ep = add2(Ep, sE);
        Fp = add2(Fp, sF);
    }

    {
        float dA, dB, gA, gB, eA, eB, fA, fB;
        unpack2(Dp, dA, dB);
        unpack2(Gp, gA, gB);
        unpack2(Ep, eA, eB);
        unpack2(Fp, fA, fB);
        const int pw = __popc(wp) & 1;
        float sDA = pw ? -dA : dA, sDB = pw ? -dB : dB;
        float* WA = &wacc[wp * 12];
        float* WB = &wacc[96 + wp * 12];
        if (lane == 31) {
            WA[0] = sDA;  WB[0] = sDB;
            WA[11] = pw ? -gA : gA;  WB[11] = pw ? -gB : gB;
        } else if (lane == 30) { WA[1] = sDA; WB[1] = sDB; }
        else if (lane == 28)   { WA[2] = sDA; WB[2] = sDB; }
        else if (lane == 24)   { WA[3] = sDA; WB[3] = sDB; }
        else if (lane == 16)   { WA[4] = sDA; WB[4] = sDB; }
        else if (lane == 0) {
            WA[5] = sDA;  WB[5] = sDB;
            int g6 = ((wp >> 1) ^ (wp >> 2)) & 1;
            WA[6] = g6 ? -dA : dA;  WB[6] = g6 ? -dB : dB;
            int g7 = (wp >> 2) & 1;
            WA[7] = g7 ? -dA : dA;  WB[7] = g7 ? -dB : dB;
            WA[8] = dA;  WB[8] = dB;
            WA[9] = eA;  WB[9] = eB;
            WA[10] = fA; WB[10] = fB;
        }
    }
    __syncthreads();
    if (tid < 24) {
        int e = tid / 12, q = tid % 12;
        float v = 0.0f;
        #pragma unroll
        for (int wi = 0; wi < 8; wi++) v += wacc[e * 96 + wi * 12 + q];
        float C = 1.0f;
        #pragma unroll
        for (int g = 0; g < 24; g++) C *= cosv[g];
        out[(2 * blk + e) * NQ + (NQ - 1 - q)] = v * (C * C);
    }
}

extern "C" void kernel_launch(void* const* d_in, const int* in_sizes, int n_in,
                              void* d_out, int out_size) {
    const float* x = (const float*)d_in[0];   // (B, 12) float32
    const float* w = (const float*)d_in[1];   // (2, 12) float32
    float* out = (float*)d_out;               // (B, 12) float32
    int B = in_sizes[0] / NQ;
    const int smem = 4096 * 16;               // 64 KB interleaved (X,Y) buffer
    cudaFuncSetAttribute(qsim_kernel, cudaFuncAttributeMaxDynamicSharedMemorySize, smem);
    qsim_kernel<<<B / 2, NT, smem>>>(x, w, out);
}

// round 14
// speedup vs baseline: 1.6552x; 1.6552x over previous
#include <cuda_runtime.h>

#define NQ 12
#define NT 256

typedef unsigned long long u64;

// ---- packed f32x2 helpers ----
static __device__ __forceinline__ u64 pack2(float lo, float hi) {
    u64 v; asm("mov.b64 %0, {%1, %2};" : "=l"(v) : "f"(lo), "f"(hi)); return v;
}
static __device__ __forceinline__ void unpack2(u64 v, float &lo, float &hi) {
    asm("mov.b64 {%0, %1}, %2;" : "=f"(lo), "=f"(hi) : "l"(v));
}
static __device__ __forceinline__ u64 fma2(u64 a, u64 b, u64 c) {
    u64 d; asm("fma.rn.f32x2 %0, %1, %2, %3;" : "=l"(d) : "l"(a), "l"(b), "l"(c)); return d;
}
static __device__ __forceinline__ u64 mul2(u64 a, u64 b) {
    u64 d; asm("mul.rn.f32x2 %0, %1, %2;" : "=l"(d) : "l"(a), "l"(b)); return d;
}
static __device__ __forceinline__ u64 add2(u64 a, u64 b) {
    u64 d; asm("add.rn.f32x2 %0, %1, %2;" : "=l"(d) : "l"(a), "l"(b)); return d;
}

#define SIGN2 0x8000000080000000ULL

// One CTA simulates TWO batch elements (lo/hi halves of every u64).
// Slot s = wp*512 + lane*16 + j. Qubit q <-> logical bit (11-q).
// Input RX(x) and layer-0 RX(w0) merge: RX(x+w0) -> closed-form product init.
// Layer-0's CNOT ring (perm P) folds into the init: slot s evaluates the
// product amplitude at bit pattern u = P(s). Layer-1 RX gates use the tangent
// form (cos factors -> global C^2 on outputs); layer-1's ring + frame f2 fold
// into the expectation signs (same tail as before).

// PJ[j] = P(j) for the 4 low slot bits (compile-time; P is GF(2)-linear).
static __device__ __constant__ const int PJ[16] = {
    0x000, 0xC01, 0x003, 0xC02, 0x006, 0xC07, 0x005, 0xC04,
    0x00C, 0xC0D, 0x00F, 0xC0E, 0x00A, 0xC0B, 0x009, 0xC08};

template<int B>
__device__ __forceinline__ void rx16(u64 (&X)[16], u64 (&Y)[16], u64 t2, u64 tn2) {
    #pragma unroll
    for (int j = 0; j < 16; j++) {
        if (!((j >> B) & 1)) {
            const int j1 = j | (1 << B);
            u64 x0 = X[j], x1 = X[j1], y0 = Y[j], y1 = Y[j1];
            X[j]  = fma2(t2,  y1, x0);
            X[j1] = fma2(t2,  y0, x1);
            Y[j]  = fma2(tn2, x1, y0);
            Y[j1] = fma2(tn2, x0, y1);
        }
    }
}

__device__ __forceinline__ void frame4(u64 (&X)[16], u64 (&Y)[16], const float2* t) {
    #pragma unroll
    for (int q = 0; q < 4; q++) {
        float2 tq = t[q];                       // (tan, -tan)
        u64 t2 = pack2(tq.x, tq.x), tn2 = pack2(tq.y, tq.y);
        if (q == 0) rx16<0>(X, Y, t2, tn2);
        else if (q == 1) rx16<1>(X, Y, t2, tn2);
        else if (q == 2) rx16<2>(X, Y, t2, tn2);
        else rx16<3>(X, Y, t2, tn2);
    }
}

__global__ void __launch_bounds__(NT, 3)
qsim_kernel(const float* __restrict__ x, const float* __restrict__ w,
            float* __restrict__ out) {
    extern __shared__ __align__(16) u64 dsm[];
    u64* sbX = dsm;                 // [4096] 32 KB
    u64* sbY = dsm + 4096;          // [4096] 32 KB
    __shared__ u64    trigC[NQ];    // packed (cosA, cosB) of merged angles
    __shared__ u64    trigS[NQ];    // packed (sinA, sinB)
    __shared__ float2 tl[NQ];       // (tan, -tan) of layer-1 gates
    __shared__ float  cosv[NQ];     // cos of layer-1 gates
    __shared__ float  wacc[2 * 8 * NQ];

    const int tid  = threadIdx.x;
    const int lane = tid & 31;
    const int wp   = tid >> 5;
    const int blk  = blockIdx.x;

    if (tid < NQ) {
        int q = tid;                        // logical bit; qubit = 11 - q
        float w0  = w[NQ - 1 - q];
        float thA = 0.5f * (x[(2 * blk) * NQ + (NQ - 1 - q)] + w0);
        float thB = 0.5f * (x[(2 * blk + 1) * NQ + (NQ - 1 - q)] + w0);
        trigC[q] = pack2(cosf(thA), cosf(thB));
        trigS[q] = pack2(sinf(thA), sinf(thB));
    } else if (tid < 2 * NQ) {
        int q = tid - NQ;
        float th = 0.5f * w[NQ + (NQ - 1 - q)];   // layer-1 row
        float c = cosf(th), s = sinf(th), tn = s / c;
        tl[q] = make_float2(tn, -tn);
        cosv[q] = c;
    }
    __syncthreads();

    u64 X[16], Y[16];

    // ---- init: product state (merged input+layer0 RX) with ring P0 folded ----
    {
        const int s_hi = (wp << 9) | (lane << 4);
        const int u_hi = ((s_hi ^ (s_hi >> 1)) & 0x3FF)
                       | ((((s_hi >> 10) ^ (s_hi >> 11) ^ s_hi) & 1) << 10)
                       | ((((s_hi >> 11) ^ s_hi) & 1) << 11);

        // fixed factor: u bits 4..9 (j-invariant)
        u64 MHI = ((u_hi >> 4) & 1) ? trigS[4] : trigC[4];
        #pragma unroll
        for (int b = 5; b <= 9; b++)
            MHI = mul2(MHI, ((u_hi >> b) & 1) ? trigS[b] : trigC[b]);
        // bits 10,11: PJ flips BOTH iff j is odd
        const int b10 = (u_hi >> 10) & 1, b11 = (u_hi >> 11) & 1;
        u64 tab_e = mul2(b10 ? trigS[10] : trigC[10], b11 ? trigS[11] : trigC[11]);
        u64 tab_o = mul2(b10 ? trigC[10] : trigS[10], b11 ? trigC[11] : trigS[11]);
        const u64 M_e = mul2(MHI, tab_e);
        const u64 M_o = mul2(MHI, tab_o);
        u64 T01[4], T23[4];
        #pragma unroll
        for (int i = 0; i < 4; i++) {
            T01[i] = mul2((i & 1) ? trigS[0] : trigC[0], (i & 2) ? trigS[1] : trigC[1]);
            T23[i] = mul2((i & 1) ? trigS[2] : trigC[2], (i & 2) ? trigS[3] : trigC[3]);
        }
        #pragma unroll
        for (int j = 0; j < 16; j++) {
            const int u = u_hi ^ PJ[j];
            u64 m = mul2(mul2((j & 1) ? M_o : M_e, T01[u & 3]), T23[(u >> 2) & 3]);
            const int pc = __popc(u) & 3;        // amp = (-i)^pc * m
            u64 mn = m ^ SIGN2;
            X[j] = (pc == 0) ? m  : (pc == 2) ? mn : 0ULL;
            Y[j] = (pc == 1) ? mn : (pc == 3) ? m  : 0ULL;
        }
    }

    // ---- layer-1 gates: frame I (logical 0-3 in regs) ----
    frame4(X, Y, &tl[0]);

    // ---- T1: swap slot bits 0-3 <-> 4-7 (warp-local: stripe bits 5-7 = wp) ----
    #pragma unroll
    for (int j = 0; j < 16; j++) {
        int a = (j << 8) | (wp << 5) | (lane ^ j);
        sbX[a] = X[j];
        sbY[a] = Y[j];
    }
    __syncwarp();
    {
        const int g = ((lane & 15) << 8) | (wp << 5) | (lane & 16);
        #pragma unroll
        for (int j = 0; j < 16; j++) {
            int a = g | (j ^ (lane & 15));
            X[j] = sbX[a];
            Y[j] = sbY[a];
        }
    }

    // ---- frame f1: logical 4-7 in regs ----
    frame4(X, Y, &tl[4]);

    // ---- T2: swap slot bits 0-3 <-> 8-11 ----
    __syncwarp();                      // T1 gather (own stripe) before overwrite
    #pragma unroll
    for (int j = 0; j < 16; j++) {
        int a = (j << 8) | (wp << 5) | (lane ^ ((j & 1) << 4));
        sbX[a] = X[j];
        sbY[a] = Y[j];
    }
    __syncthreads();
    {
        const int ru = (lane >> 4) | (wp << 1);
        #pragma unroll
        for (int j = 0; j < 16; j++) {
            int a = (ru << 8) | ((j >> 1) << 5) | (lane & 15)
                  | (((j & 1) ^ (lane >> 4)) << 4);
            X[j] = sbX[a];
            Y[j] = sbY[a];
        }
    }

    // ---- frame f2: logical 8-11 in regs ----
    frame4(X, Y, &tl[8]);

    // ---- expectations (frame f2 + pending layer-1 ring folded into signs) ----
    const u64 one2  = pack2(1.0f, 1.0f);
    const u64 mone2 = pack2(-1.0f, -1.0f);
    u64 Dp, Ep, Fp, Gp;
    {
        u64 P0 = fma2(X[0], X[0], mul2(Y[0], Y[0]));
        Dp = P0; Ep = P0; Fp = P0; Gp = P0;
    }
    #pragma unroll
    for (int j = 1; j < 16; j++) {
        u64 P = fma2(X[j], X[j], mul2(Y[j], Y[j]));
        Dp = fma2((__popc(j)      & 1) ? mone2 : one2, P, Dp);  // r0^r1^r2^r3
        Ep = fma2((__popc(j & 14) & 1) ? mone2 : one2, P, Ep);  // r1^r2^r3
        Fp = fma2((__popc(j & 12) & 1) ? mone2 : one2, P, Fp);  // r2^r3
        Gp = fma2((__popc(j & 7)  & 1) ? mone2 : one2, P, Gp);  // r0^r1^r2
    }

    // Walsh-Hadamard over the 5 lane bits on D and G; allreduce on E, F.
    #pragma unroll
    for (int st = 0; st < 5; st++) {
        const int m = 1 << st;
        u64 sD = __shfl_xor_sync(0xffffffffu, Dp, m);
        u64 sG = __shfl_xor_sync(0xffffffffu, Gp, m);
        u64 sE = __shfl_xor_sync(0xffffffffu, Ep, m);
        u64 sF = __shfl_xor_sync(0xffffffffu, Fp, m);
        u64 sgn = (lane & m) ? mone2 : one2;
        Dp = fma2(sgn, Dp, sD);
        Gp = fma2(sgn, Gp, sG);
        Ep = add2(Ep, sE);
        Fp = add2(Fp, sF);
    }

    {
        float dA, dB, gA, gB, eA, eB, fA, fB;
        unpack2(Dp, dA, dB);
        unpack2(Gp, gA, gB);
        unpack2(Ep, eA, eB);
        unpack2(Fp, fA, fB);
        const int pw = __popc(wp) & 1;
        float sDA = pw ? -dA : dA, sDB = pw ? -dB : dB;
        float* WA = &wacc[wp * 12];
        float* WB = &wacc[96 + wp * 12];
        if (lane == 31) {
            WA[0] = sDA;  WB[0] = sDB;
            WA[11] = pw ? -gA : gA;  WB[11] = pw ? -gB : gB;
        } else if (lane == 30) { WA[1] = sDA; WB[1] = sDB; }
        else if (lane == 28)   { WA[2] = sDA; WB[2] = sDB; }
        else if (lane == 24)   { WA[3] = sDA; WB[3] = sDB; }
        else if (lane == 16)   { WA[4] = sDA; WB[4] = sDB; }
        else if (lane == 0) {
            WA[5] = sDA;  WB[5] = sDB;
            int g6 = ((wp >> 1) ^ (wp >> 2)) & 1;
            WA[6] = g6 ? -dA : dA;  WB[6] = g6 ? -dB : dB;
            int g7 = (wp >> 2) & 1;
            WA[7] = g7 ? -dA : dA;  WB[7] = g7 ? -dB : dB;
            WA[8] = dA;  WB[8] = dB;
            WA[9] = eA;  WB[9] = eB;
            WA[10] = fA; WB[10] = fB;
        }
    }
    __syncthreads();
    if (tid < 2 * NQ) {
        int e = tid / NQ, q = tid % NQ;
        float v = 0.0f;
        #pragma unroll
        for (int wi = 0; wi < 8; wi++) v += wacc[e * 96 + wi * 12 + q];
        float C = 1.0f;
        #pragma unroll
        for (int g = 0; g < NQ; g++) C *= cosv[g];
        out[(2 * blk + e) * NQ + (NQ - 1 - q)] = v * (C * C);
    }
}

extern "C" void kernel_launch(void* const* d_in, const int* in_sizes, int n_in,
                              void* d_out, int out_size) {
    const float* x = (const float*)d_in[0];   // (B, 12) float32
    const float* w = (const float*)d_in[1];   // (2, 12) float32
    float* out = (float*)d_out;               // (B, 12) float32
    int B = in_sizes[0] / NQ;
    const int smem = 4096 * 8 * 2;            // 64 KB state buffer
    cudaFuncSetAttribute(qsim_kernel, cudaFuncAttributeMaxDynamicSharedMemorySize, smem);
    qsim_kernel<<<B / 2, NT, smem>>>(x, w, out);
}